// round 7
// baseline (speedup 1.0000x reference)
#include <cuda_runtime.h>

#define NIMG 8
#define NA   25200
#define NCLS 80
#define ROWL 85
#define DETN 300
#define CONF 0.96f
#define IOUT 0.45f
#define BCAP 128            // per-(img,class) bucket capacity (E~20, sigma~4.5)
#define KCAP 2048           // per-image kept capacity
#define NBUCK 4096
#define NANCH (NIMG * NA)   // 201600

typedef unsigned long long u64;

// ---------------- device scratch (zero-initialized at module load;
// consumers reset what they read, so every graph replay starts clean) ------
__device__ int g_ccount[NIMG * NCLS];
__device__ u64 g_bucket[NIMG * NCLS * BCAP];

// ---------------- K1: extraction — 4 anchors per thread (MLP=4)
__global__ __launch_bounds__(256) void k_extract(const float* __restrict__ pred) {
    int tid  = threadIdx.x;
    int lane = tid & 31;
    int blk  = blockIdx.x * 1024;

    // front-batched independent loads -> 4 outstanding LDGs per thread
    int   idx[4];
    float obj[4];
    bool  hotf[4];
    #pragma unroll
    for (int i = 0; i < 4; i++) {
        idx[i] = blk + tid + 256 * i;
        bool v = idx[i] < NANCH;
        obj[i] = v ? __ldg(pred + (size_t)idx[i] * ROWL + 4) : 0.f;
        hotf[i] = v && obj[i] > CONF;
    }

    #pragma unroll
    for (int i = 0; i < 4; i++) {
        unsigned hot = __ballot_sync(0xFFFFFFFFu, hotf[i]);
        while (hot) {
            int src = __ffs(hot) - 1;
            hot &= hot - 1;
            int aidx = __shfl_sync(0xFFFFFFFFu, idx[i], src);
            float o  = __shfl_sync(0xFFFFFFFFu, obj[i], src);
            const float* r = pred + (size_t)aidx * ROWL;
            int img = aidx / NA;
            int a   = aidx - img * NA;
            #pragma unroll
            for (int base = 0; base < 96; base += 32) {
                int c = base + lane;
                if (c < NCLS) {
                    float s = __fmul_rn(__ldg(r + 5 + c), o);
                    if (s > CONF) {
                        unsigned fi = (unsigned)(a * NCLS + c);
                        u64 key = ((u64)__float_as_uint(s) << 32)
                                  | (u64)(0xFFFFFFFFu - fi);
                        int slot = atomicAdd(&g_ccount[img * NCLS + c], 1);
                        if (slot < BCAP)
                            g_bucket[(size_t)(img * NCLS + c) * BCAP + slot] = key;
                    }
                }
            }
        }
    }
}

// ---------------- K2: fused per-image NMS + top-300 selection
// grid = NIMG, 1024 threads, ~156 KB dynamic smem (1 block/SM; grid=8 so
// occupancy is irrelevant). Warp w handles classes w, w+32, w+64.
//
// dynamic smem layout (all offsets 16B-aligned):
//   [0      , 32768 ) skey  : u64  [32][BCAP]
//   [32768  , 98304 ) snb   : f4   [32][BCAP]
//   [98304  , 114688) sarea : f32  [32][BCAP]
//   [114688 , 118784) skeep : u8   [32][BCAP]
//   [118784 , 135168) kept  : u64  [KCAP]
//   [135168 , 151552) hist  : i32  [NBUCK]
//   [151552 , 155648) ssuf  : i32  [1024]
//   [155648 , 159744) cand  : u64  [512]
#define SMEM_BYTES 159744

__global__ __launch_bounds__(1024, 1) void k_image(const float* __restrict__ pred,
                                                   float* __restrict__ out) {
    extern __shared__ char dsm[];
    u64*           skeyA  = (u64*)(dsm);
    float4*        snbA   = (float4*)(dsm + 32768);
    float*         sareaA = (float*)(dsm + 98304);
    unsigned char* skeepA = (unsigned char*)(dsm + 114688);
    u64*           kept   = (u64*)(dsm + 118784);
    int*           hist   = (int*)(dsm + 135168);
    int*           ssuf   = (int*)(dsm + 151552);
    u64*           cand   = (u64*)(dsm + 155648);
    __shared__ int s_kcnt, sB, scnt;

    int img  = blockIdx.x;
    int tid  = threadIdx.x;
    int wid  = tid >> 5;
    int lane = tid & 31;

    if (tid == 0) { s_kcnt = 0; scnt = 0; sB = 0; }
    for (int i = tid; i < NBUCK; i += 1024) hist[i] = 0;
    __syncthreads();

    u64*           skey  = skeyA  + wid * BCAP;
    float4*        snb   = snbA   + wid * BCAP;
    float*         sarea = sareaA + wid * BCAP;
    unsigned char* skeep = skeepA + wid * BCAP;

    // ---------- phase 1: per-class sort + greedy NMS (warp-local) ----------
    for (int round = 0; round < 3; round++) {
        int cls = wid + 32 * round;
        if (cls >= NCLS) break;
        int ww = img * NCLS + cls;

        int m = 0;
        if (lane == 0) {                     // single-owner read + reset
            m = g_ccount[ww];
            if (m > 0) g_ccount[ww] = 0;
        }
        m = __shfl_sync(0xFFFFFFFFu, m, 0);
        if (m > BCAP) m = BCAP;

        const u64* bucket = g_bucket + (size_t)ww * BCAP;
        for (int t = lane; t < BCAP; t += 32)
            skey[t] = (t < m) ? bucket[t] : 0ULL;
        __syncwarp();
        if (m == 0) continue;

        // bitonic sort desc over 128 unique keys (zeros sink to the tail)
        for (int k = 2; k <= BCAP; k <<= 1) {
            for (int j = k >> 1; j > 0; j >>= 1) {
                for (int t = lane; t < BCAP; t += 32) {
                    int x = t ^ j;
                    if (x > t) {
                        u64 va = skey[t], vb = skey[x];
                        bool up = ((t & k) == 0);
                        if ((va < vb) == up) { skey[t] = vb; skey[x] = va; }
                    }
                }
                __syncwarp();
            }
        }

        // decode offset boxes + areas (exact reference fp expression order)
        float off = __fmul_rn((float)cls, 4.0f);
        for (int t = lane; t < m; t += 32) {
            unsigned fi = 0xFFFFFFFFu - (unsigned)(skey[t] & 0xFFFFFFFFull);
            int anchor = (int)(fi / NCLS);
            const float* r = pred + ((size_t)img * NA + anchor) * ROWL;
            float cx = __ldg(r), cy = __ldg(r + 1), w2 = __ldg(r + 2), h2 = __ldg(r + 3);
            float hw = __fmul_rn(0.5f, w2);
            float hv = __fmul_rn(0.5f, h2);
            float4 nb;
            nb.x = __fadd_rn(__fsub_rn(cx, hw), off);
            nb.y = __fadd_rn(__fsub_rn(cy, hv), off);
            nb.z = __fadd_rn(__fadd_rn(cx, hw), off);
            nb.w = __fadd_rn(__fadd_rn(cy, hv), off);
            snb[t]   = nb;
            sarea[t] = __fmul_rn(__fsub_rn(nb.z, nb.x), __fsub_rn(nb.w, nb.y));
            skeep[t] = 1;
        }
        __syncwarp();

        // greedy NMS in sorted order (== global sequential scan within class;
        // cross-class IoU is exactly 0 under the label*4 offset)
        for (int i = 0; i < m; i++) {
            if (skeep[i]) {
                float4 bi = snb[i];
                float  ai = sarea[i];
                for (int t = i + 1 + lane; t < m; t += 32) {
                    if (skeep[t]) {
                        float4 bt = snb[t];
                        float lx = fmaxf(bi.x, bt.x), ly = fmaxf(bi.y, bt.y);
                        float rx = fminf(bi.z, bt.z), ry = fminf(bi.w, bt.w);
                        float iw = fmaxf(__fsub_rn(rx, lx), 0.f);
                        float ih = fmaxf(__fsub_rn(ry, ly), 0.f);
                        float inter = __fmul_rn(iw, ih);
                        float den = __fadd_rn(
                            __fsub_rn(__fadd_rn(ai, sarea[t]), inter), 1e-9f);
                        if (__fdiv_rn(inter, den) > IOUT) skeep[t] = 0;
                    }
                }
            }
            __syncwarp();
        }

        // push kept keys to the shared per-image list
        for (int base = 0; base < BCAP; base += 32) {
            int t = base + lane;
            bool k = (t < m) && skeep[t];
            unsigned bal = __ballot_sync(0xFFFFFFFFu, k);
            int cnt = __popc(bal);
            if (cnt) {
                int pos = 0;
                if (lane == 0) pos = atomicAdd(&s_kcnt, cnt);
                pos = __shfl_sync(0xFFFFFFFFu, pos, 0);
                int rank = pos + __popc(bal & ((1u << lane) - 1u));
                if (k && rank < KCAP) kept[rank] = skey[t];
            }
            if (base + 32 >= m) break;
        }
    }
    __syncthreads();

    // ---------- phase 2: histogram top-300 selection + small sort ----------
    // scores in (0.96, 1.0) -> fp32 exponent fixed -> key bits [54:43]
    // (score-mantissa top 12) are monotonic in score.
    int kc = s_kcnt; if (kc > KCAP) kc = KCAP;
    for (int i = tid; i < kc; i += 1024) {
        unsigned h = (unsigned)(kept[i] >> 43) & 0xFFFu;
        atomicAdd(&hist[h], 1);
    }
    __syncthreads();

    int need = (kc < DETN) ? kc : DETN;

    int b0 = tid * 4;
    int c0 = hist[b0], c1 = hist[b0 + 1], c2 = hist[b0 + 2], c3 = hist[b0 + 3];
    ssuf[tid] = c0 + c1 + c2 + c3;
    __syncthreads();
    for (int d = 1; d < 1024; d <<= 1) {
        int v = ssuf[tid];
        int w = (tid + d < 1024) ? ssuf[tid + d] : 0;
        __syncthreads();
        ssuf[tid] = v + w;
        __syncthreads();
    }
    int above = (tid < 1023) ? ssuf[tid + 1] : 0;

    if (need > 0) {          // unique B*: suf(B*) >= need, suf(B*+1) < need
        int s3 = above + c3;
        int s2 = s3 + c2;
        int s1 = s2 + c1;
        int s0 = s1 + c0;
        if      (s3 >= need && above < need) sB = b0 + 3;
        else if (s2 >= need && s3 < need)    sB = b0 + 2;
        else if (s1 >= need && s2 < need)    sB = b0 + 1;
        else if (s0 >= need && s1 < need)    sB = b0;
    }
    __syncthreads();

    int B = sB;
    if (need > 0) {
        for (int i = tid; i < kc; i += 1024) {
            u64 key = kept[i];
            unsigned h = (unsigned)(key >> 43) & 0xFFFu;
            if ((int)h >= B) {
                int p = atomicAdd(&scnt, 1);
                if (p < 512) cand[p] = key;
            }
        }
    }
    __syncthreads();
    int nc = scnt; if (nc > 512) nc = 512;
    for (int i = tid; i < 512; i += 1024) if (i >= nc) cand[i] = 0ULL;
    __syncthreads();

    // bitonic sort 512 desc (unique keys -> deterministic)
    for (int k = 2; k <= 512; k <<= 1) {
        for (int j = k >> 1; j > 0; j >>= 1) {
            if (tid < 512) {
                int t = tid;
                int x = t ^ j;
                if (x > t) {
                    u64 va = cand[t], vb = cand[x];
                    bool up = ((t & k) == 0);
                    if ((va < vb) == up) { cand[t] = vb; cand[x] = va; }
                }
            }
            __syncthreads();
        }
    }

    // decode + write top-300 (rows >= need zeroed)
    for (int r = tid; r < DETN; r += 1024) {
        float o0 = 0.f, o1 = 0.f, o2 = 0.f, o3 = 0.f, o4 = 0.f, o5 = 0.f;
        if (r < need) {
            u64 key = cand[r];
            float sc = __uint_as_float((unsigned)(key >> 32));
            unsigned fi = 0xFFFFFFFFu - (unsigned)(key & 0xFFFFFFFFull);
            int anchor = (int)(fi / NCLS);
            int label  = (int)(fi - (unsigned)anchor * NCLS);
            const float* rr = pred + ((size_t)img * NA + anchor) * ROWL;
            float cx = __ldg(rr), cy = __ldg(rr + 1), w2 = __ldg(rr + 2), h2 = __ldg(rr + 3);
            float hw = __fmul_rn(0.5f, w2);
            float hv = __fmul_rn(0.5f, h2);
            o0 = __fsub_rn(cx, hw); o1 = __fsub_rn(cy, hv);
            o2 = __fadd_rn(cx, hw); o3 = __fadd_rn(cy, hv);
            o4 = sc; o5 = (float)label;
        }
        float* dst = out + ((size_t)img * DETN + r) * 6;
        dst[0] = o0; dst[1] = o1; dst[2] = o2;
        dst[3] = o3; dst[4] = o4; dst[5] = o5;
    }
}

// ---------------- launcher ----------------
extern "C" void kernel_launch(void* const* d_in, const int* in_sizes, int n_in,
                              void* d_out, int out_size) {
    const float* pred = (const float*)d_in[0];
    float* out = (float*)d_out;
    (void)in_sizes; (void)n_in; (void)out_size;

    cudaFuncSetAttribute(k_image, cudaFuncAttributeMaxDynamicSharedMemorySize,
                         SMEM_BYTES);                      // idempotent, no alloc

    k_extract<<<(NANCH + 1023) / 1024, 256>>>(pred);       // 197 blocks, 4 anchors/thread
    k_image<<<NIMG, 1024, SMEM_BYTES>>>(pred, out);        // fused NMS + top-300
}

// round 8
// speedup vs baseline: 1.8823x; 1.8823x over previous
#include <cuda_runtime.h>

#define NIMG 8
#define NA   25200
#define NCLS 80
#define ROWL 85
#define DETN 300
#define CONF 0.96f
#define IOUT 0.45f
#define BCAP 128            // per-(img,class) bucket capacity (E~20, sigma~4.5)
#define KCAP 2048           // per-image kept capacity
#define NBUCK 4096
#define NANCH (NIMG * NA)   // 201600

typedef unsigned long long u64;

// ---------------- device scratch (zero-initialized at module load;
// consumers reset what they read, so every graph replay starts clean) ------
__device__ int g_ccount[NIMG * NCLS];
__device__ u64 g_bucket[NIMG * NCLS * BCAP];
__device__ int g_kcount[NIMG];
__device__ u64 g_kept[NIMG * KCAP];

// ---------------- K1: extraction — 4 anchors per thread (MLP=4)
__global__ __launch_bounds__(256) void k_extract(const float* __restrict__ pred) {
    int tid  = threadIdx.x;
    int lane = tid & 31;
    int blk  = blockIdx.x * 1024;

    // front-batched independent loads -> 4 outstanding LDGs per thread
    int   idx[4];
    float obj[4];
    bool  hotf[4];
    #pragma unroll
    for (int i = 0; i < 4; i++) {
        idx[i] = blk + tid + 256 * i;
        bool v = idx[i] < NANCH;
        obj[i] = v ? __ldg(pred + (size_t)idx[i] * ROWL + 4) : 0.f;
        hotf[i] = v && obj[i] > CONF;
    }

    #pragma unroll
    for (int i = 0; i < 4; i++) {
        unsigned hot = __ballot_sync(0xFFFFFFFFu, hotf[i]);
        while (hot) {
            int src = __ffs(hot) - 1;
            hot &= hot - 1;
            int aidx = __shfl_sync(0xFFFFFFFFu, idx[i], src);
            float o  = __shfl_sync(0xFFFFFFFFu, obj[i], src);
            const float* r = pred + (size_t)aidx * ROWL;
            int img = aidx / NA;
            int a   = aidx - img * NA;
            #pragma unroll
            for (int base = 0; base < 96; base += 32) {
                int c = base + lane;
                if (c < NCLS) {
                    float s = __fmul_rn(__ldg(r + 5 + c), o);
                    if (s > CONF) {
                        unsigned fi = (unsigned)(a * NCLS + c);
                        u64 key = ((u64)__float_as_uint(s) << 32)
                                  | (u64)(0xFFFFFFFFu - fi);
                        int slot = atomicAdd(&g_ccount[img * NCLS + c], 1);
                        if (slot < BCAP)
                            g_bucket[(size_t)(img * NCLS + c) * BCAP + slot] = key;
                    }
                }
            }
        }
    }
}

// ---------------- K2: per-(img,class) sort + greedy NMS — one warp each
__global__ __launch_bounds__(128) void k_nms(const float* __restrict__ pred) {
    __shared__ u64    skey[4][BCAP];
    __shared__ float4 snb[4][BCAP];
    __shared__ float  sarea[4][BCAP];
    __shared__ unsigned char skeep[4][BCAP];

    int ws   = threadIdx.x >> 5;
    int lane = threadIdx.x & 31;
    int ww   = blockIdx.x * 4 + ws;          // (img, cls) id
    int img  = ww / NCLS;
    int cls  = ww - img * NCLS;

    int m = 0;
    if (lane == 0) {                         // single-owner read + reset
        m = g_ccount[ww];
        if (m > 0) g_ccount[ww] = 0;
    }
    m = __shfl_sync(0xFFFFFFFFu, m, 0);
    if (m > BCAP) m = BCAP;

    const u64* bucket = g_bucket + (size_t)ww * BCAP;
    for (int t = lane; t < BCAP; t += 32)
        skey[ws][t] = (t < m) ? bucket[t] : 0ULL;
    __syncwarp();
    if (m == 0) return;

    // bitonic sort desc over 128 unique keys (zeros sink to the tail)
    for (int k = 2; k <= BCAP; k <<= 1) {
        for (int j = k >> 1; j > 0; j >>= 1) {
            for (int t = lane; t < BCAP; t += 32) {
                int x = t ^ j;
                if (x > t) {
                    u64 va = skey[ws][t], vb = skey[ws][x];
                    bool up = ((t & k) == 0);
                    if ((va < vb) == up) { skey[ws][t] = vb; skey[ws][x] = va; }
                }
            }
            __syncwarp();
        }
    }

    // decode offset boxes + areas (exact reference fp expression order)
    float off = __fmul_rn((float)cls, 4.0f);
    for (int t = lane; t < m; t += 32) {
        unsigned fi = 0xFFFFFFFFu - (unsigned)(skey[ws][t] & 0xFFFFFFFFull);
        int anchor = (int)(fi / NCLS);
        const float* r = pred + ((size_t)img * NA + anchor) * ROWL;
        float cx = __ldg(r), cy = __ldg(r + 1), w2 = __ldg(r + 2), h2 = __ldg(r + 3);
        float hw = __fmul_rn(0.5f, w2);
        float hv = __fmul_rn(0.5f, h2);
        float4 nb;
        nb.x = __fadd_rn(__fsub_rn(cx, hw), off);
        nb.y = __fadd_rn(__fsub_rn(cy, hv), off);
        nb.z = __fadd_rn(__fadd_rn(cx, hw), off);
        nb.w = __fadd_rn(__fadd_rn(cy, hv), off);
        snb[ws][t]   = nb;
        sarea[ws][t] = __fmul_rn(__fsub_rn(nb.z, nb.x), __fsub_rn(nb.w, nb.y));
        skeep[ws][t] = 1;
    }
    __syncwarp();

    // greedy NMS in sorted order (== global sequential scan within class;
    // cross-class IoU is exactly 0 under the label*4 offset)
    for (int i = 0; i < m; i++) {
        if (skeep[ws][i]) {
            float4 bi = snb[ws][i];
            float  ai = sarea[ws][i];
            for (int t = i + 1 + lane; t < m; t += 32) {
                if (skeep[ws][t]) {
                    float4 bt = snb[ws][t];
                    float lx = fmaxf(bi.x, bt.x), ly = fmaxf(bi.y, bt.y);
                    float rx = fminf(bi.z, bt.z), ry = fminf(bi.w, bt.w);
                    float iw = fmaxf(__fsub_rn(rx, lx), 0.f);
                    float ih = fmaxf(__fsub_rn(ry, ly), 0.f);
                    float inter = __fmul_rn(iw, ih);
                    float den = __fadd_rn(
                        __fsub_rn(__fadd_rn(ai, sarea[ws][t]), inter), 1e-9f);
                    if (__fdiv_rn(inter, den) > IOUT) skeep[ws][t] = 0;
                }
            }
        }
        __syncwarp();
    }

    // push kept keys to the per-image list (rank restored in k_final by key)
    for (int base = 0; base < BCAP; base += 32) {
        int t = base + lane;
        bool k = (t < m) && skeep[ws][t];
        unsigned bal = __ballot_sync(0xFFFFFFFFu, k);
        int cnt = __popc(bal);
        if (cnt) {
            int pos = 0;
            if (lane == 0) pos = atomicAdd(&g_kcount[img], cnt);
            pos = __shfl_sync(0xFFFFFFFFu, pos, 0);
            int rank = pos + __popc(bal & ((1u << lane) - 1u));
            if (k && rank < KCAP) g_kept[(size_t)img * KCAP + rank] = skey[ws][t];
        }
        if (base + 32 >= m) break;
    }
}

// ---------------- K3: bucket-scatter top-300 (7 barriers, no big sort)
// scores in (0.96,1) -> fp32 sign/exponent fixed -> key order ==
// (bucket = key bits [54:43], residual key) lexicographic, descending.
__global__ __launch_bounds__(256) void k_final(const float* __restrict__ pred,
                                               float* __restrict__ out) {
    __shared__ int hist[NBUCK];              // counts -> then exclusive-above offsets
    __shared__ int warp_sum[8], warp_suf[8];
    __shared__ u64 cand[512];
    __shared__ int sB, skc;

    int img  = blockIdx.x;
    int tid  = threadIdx.x;
    int wid  = tid >> 5;
    int lane = tid & 31;

    if (tid == 0) {                          // single-owner read + reset
        int k = g_kcount[img];
        g_kcount[img] = 0;
        skc = (k > KCAP) ? KCAP : k;
        sB = 0;
    }
    for (int i = tid; i < NBUCK; i += 256) hist[i] = 0;
    __syncthreads();                                              // BAR1
    int kc = skc;
    int need = (kc < DETN) ? kc : DETN;

    const u64* kept = g_kept + (size_t)img * KCAP;
    for (int i = tid; i < kc; i += 256)
        atomicAdd(&hist[(unsigned)(kept[i] >> 43) & 0xFFFu], 1);
    __syncthreads();                                              // BAR2

    // thread owns 16 consecutive buckets [tid*16, tid*16+16)
    int base = tid * 16;
    int c[16]; int csum = 0;
    #pragma unroll
    for (int j = 0; j < 16; j++) { c[j] = hist[base + j]; csum += c[j]; }

    // warp inclusive-suffix scan of per-thread sums
    int v = csum;
    #pragma unroll
    for (int d = 1; d < 32; d <<= 1) {
        int u = __shfl_down_sync(0xFFFFFFFFu, v, d);
        if (lane + d < 32) v += u;
    }
    if (lane == 0) warp_sum[wid] = v;        // warp total
    __syncthreads();                                              // BAR3
    if (tid < 8) {
        int s = 0;
        for (int w = tid + 1; w < 8; w++) s += warp_sum[w];
        warp_suf[tid] = s;                   // totals of higher warps
    }
    __syncthreads();                                              // BAR4

    // per-bucket exclusive-above offsets (stored back into hist) + find B*
    int run = (v - csum) + warp_suf[wid];    // strictly-above this thread's chunk
    #pragma unroll
    for (int j = 15; j >= 0; j--) {
        int excl = run;
        run += c[j];
        hist[base + j] = excl;
        if (need > 0 && run >= need && excl < need) sB = base + j;  // unique
    }
    __syncthreads();                                              // BAR5

    // scatter keys >= B* into per-bucket slots (disjoint ranges)
    int B = sB;
    for (int i = tid; i < kc; i += 256) {
        u64 key = kept[i];
        int h = (int)((unsigned)(key >> 43) & 0xFFFu);
        if (h >= B) {
            int p = atomicAdd(&hist[h], 1);
            if (p < 512) cand[p] = key;
        }
    }
    __syncthreads();                                              // BAR6

    // deterministic within-bucket order: tiny insertion sorts (desc)
    for (int h = tid; h < NBUCK; h += 256) {
        if (h >= B) {
            int hi = hist[h]; if (hi > 512) hi = 512;
            int lo = (h < NBUCK - 1) ? hist[h + 1] : 0;
            if (lo > 512) lo = 512;
            for (int a = lo + 1; a < hi; a++) {
                u64 key = cand[a];
                int b = a;
                while (b > lo && cand[b - 1] < key) { cand[b] = cand[b - 1]; b--; }
                cand[b] = key;
            }
        }
    }
    __syncthreads();                                              // BAR7

    // decode + write top-300 (rows >= need zeroed)
    for (int r = tid; r < DETN; r += 256) {
        float o0 = 0.f, o1 = 0.f, o2 = 0.f, o3 = 0.f, o4 = 0.f, o5 = 0.f;
        if (r < need) {
            u64 key = cand[r];
            float sc = __uint_as_float((unsigned)(key >> 32));
            unsigned fi = 0xFFFFFFFFu - (unsigned)(key & 0xFFFFFFFFull);
            int anchor = (int)(fi / NCLS);
            int label  = (int)(fi - (unsigned)anchor * NCLS);
            const float* rr = pred + ((size_t)img * NA + anchor) * ROWL;
            float cx = __ldg(rr), cy = __ldg(rr + 1), w2 = __ldg(rr + 2), h2 = __ldg(rr + 3);
            float hw = __fmul_rn(0.5f, w2);
            float hv = __fmul_rn(0.5f, h2);
            o0 = __fsub_rn(cx, hw); o1 = __fsub_rn(cy, hv);
            o2 = __fadd_rn(cx, hw); o3 = __fadd_rn(cy, hv);
            o4 = sc; o5 = (float)label;
        }
        float* dst = out + ((size_t)img * DETN + r) * 6;
        dst[0] = o0; dst[1] = o1; dst[2] = o2;
        dst[3] = o3; dst[4] = o4; dst[5] = o5;
    }
}

// ---------------- launcher ----------------
extern "C" void kernel_launch(void* const* d_in, const int* in_sizes, int n_in,
                              void* d_out, int out_size) {
    const float* pred = (const float*)d_in[0];
    float* out = (float*)d_out;
    (void)in_sizes; (void)n_in; (void)out_size;

    k_extract<<<(NANCH + 1023) / 1024, 256>>>(pred);   // 197 blocks, 4 anchors/thread
    k_nms<<<(NIMG * NCLS) / 4, 128>>>(pred);           // 160 blocks, 1 warp/(img,cls)
    k_final<<<NIMG, 256>>>(pred, out);                 // 7-barrier bucket ranking
}

// round 9
// speedup vs baseline: 1.8889x; 1.0035x over previous
#include <cuda_runtime.h>

#define NIMG 8
#define NA   25200
#define NCLS 80
#define ROWL 85
#define DETN 300
#define CONF 0.96f
#define IOUT 0.45f
#define BCAP 128            // per-(img,class) bucket capacity (E~20, sigma~4.5)
#define KCAP 2048           // per-image kept capacity
#define NBUCK 4096
#define NANCH (NIMG * NA)   // 201600
#define NHOT  16384         // hot-anchor list capacity (E~8064, sd~88)

typedef unsigned long long u64;

// ---------------- device scratch (zero-initialized at module load;
// consumers reset what they read, so every graph replay starts clean) ------
__device__ int g_ccount[NIMG * NCLS];
__device__ u64 g_bucket[NIMG * NCLS * BCAP];
__device__ int g_kcount[NIMG];
__device__ u64 g_kept[NIMG * KCAP];
__device__ int g_hotcnt;
__device__ u64 g_hot[NHOT];              // (obj_bits << 32) | anchor_idx

// ---------------- K1a: pure obj scan — 296 blocks (2/SM), 3 loads/thread
__global__ __launch_bounds__(256) void k_scan(const float* __restrict__ pred) {
    int tid  = threadIdx.x;
    int lane = tid & 31;
    int base = blockIdx.x * 768;

    int   idx[3];
    float obj[3];
    bool  hot[3];
    #pragma unroll
    for (int i = 0; i < 3; i++) {        // front-batched independent LDGs
        idx[i] = base + tid + 256 * i;
        bool v = idx[i] < NANCH;
        obj[i] = v ? __ldg(pred + (size_t)idx[i] * ROWL + 4) : 0.f;
        hot[i] = v && obj[i] > CONF;
    }

    #pragma unroll
    for (int i = 0; i < 3; i++) {        // warp-aggregated push of hot anchors
        unsigned bal = __ballot_sync(0xFFFFFFFFu, hot[i]);
        int cnt = __popc(bal);
        if (cnt) {
            int pos = 0;
            if (lane == 0) pos = atomicAdd(&g_hotcnt, cnt);
            pos = __shfl_sync(0xFFFFFFFFu, pos, 0);
            int rank = pos + __popc(bal & ((1u << lane) - 1u));
            if (hot[i] && rank < NHOT)
                g_hot[rank] = ((u64)__float_as_uint(obj[i]) << 32) | (u64)idx[i];
        }
    }
}

// ---------------- K1b: hot-row processing — one warp per hot anchor (strided)
__global__ __launch_bounds__(256) void k_hot(const float* __restrict__ pred) {
    int gw   = (blockIdx.x * 256 + threadIdx.x) >> 5;   // global warp id
    int lane = threadIdx.x & 31;
    const int nwarps = 252 * 8;

    int cnt = g_hotcnt;                  // written by k_scan (kernel boundary)
    if (cnt > NHOT) cnt = NHOT;

    for (int h = gw; h < cnt; h += nwarps) {
        u64 e = g_hot[h];
        int   aidx = (int)(e & 0xFFFFFFFFull);
        float o    = __uint_as_float((unsigned)(e >> 32));
        const float* r = pred + (size_t)aidx * ROWL;
        int img = aidx / NA;
        int a   = aidx - img * NA;
        #pragma unroll
        for (int base = 0; base < 96; base += 32) {
            int c = base + lane;
            if (c < NCLS) {
                float s = __fmul_rn(__ldg(r + 5 + c), o);
                if (s > CONF) {
                    unsigned fi = (unsigned)(a * NCLS + c);
                    u64 key = ((u64)__float_as_uint(s) << 32)
                              | (u64)(0xFFFFFFFFu - fi);
                    int slot = atomicAdd(&g_ccount[img * NCLS + c], 1);
                    if (slot < BCAP)
                        g_bucket[(size_t)(img * NCLS + c) * BCAP + slot] = key;
                }
            }
        }
    }
}

// ---------------- K2: per-(img,class) sort + greedy NMS — one warp each
__global__ __launch_bounds__(128) void k_nms(const float* __restrict__ pred) {
    __shared__ u64    skey[4][BCAP];
    __shared__ float4 snb[4][BCAP];
    __shared__ float  sarea[4][BCAP];
    __shared__ unsigned char skeep[4][BCAP];

    int ws   = threadIdx.x >> 5;
    int lane = threadIdx.x & 31;
    int ww   = blockIdx.x * 4 + ws;          // (img, cls) id
    int img  = ww / NCLS;
    int cls  = ww - img * NCLS;

    int m = 0;
    if (lane == 0) {                         // single-owner read + reset
        m = g_ccount[ww];
        if (m > 0) g_ccount[ww] = 0;
    }
    m = __shfl_sync(0xFFFFFFFFu, m, 0);
    if (m > BCAP) m = BCAP;

    const u64* bucket = g_bucket + (size_t)ww * BCAP;
    for (int t = lane; t < BCAP; t += 32)
        skey[ws][t] = (t < m) ? bucket[t] : 0ULL;
    __syncwarp();
    if (m == 0) return;

    // bitonic sort desc over 128 unique keys (zeros sink to the tail)
    for (int k = 2; k <= BCAP; k <<= 1) {
        for (int j = k >> 1; j > 0; j >>= 1) {
            for (int t = lane; t < BCAP; t += 32) {
                int x = t ^ j;
                if (x > t) {
                    u64 va = skey[ws][t], vb = skey[ws][x];
                    bool up = ((t & k) == 0);
                    if ((va < vb) == up) { skey[ws][t] = vb; skey[ws][x] = va; }
                }
            }
            __syncwarp();
        }
    }

    // decode offset boxes + areas (exact reference fp expression order)
    float off = __fmul_rn((float)cls, 4.0f);
    for (int t = lane; t < m; t += 32) {
        unsigned fi = 0xFFFFFFFFu - (unsigned)(skey[ws][t] & 0xFFFFFFFFull);
        int anchor = (int)(fi / NCLS);
        const float* r = pred + ((size_t)img * NA + anchor) * ROWL;
        float cx = __ldg(r), cy = __ldg(r + 1), w2 = __ldg(r + 2), h2 = __ldg(r + 3);
        float hw = __fmul_rn(0.5f, w2);
        float hv = __fmul_rn(0.5f, h2);
        float4 nb;
        nb.x = __fadd_rn(__fsub_rn(cx, hw), off);
        nb.y = __fadd_rn(__fsub_rn(cy, hv), off);
        nb.z = __fadd_rn(__fadd_rn(cx, hw), off);
        nb.w = __fadd_rn(__fadd_rn(cy, hv), off);
        snb[ws][t]   = nb;
        sarea[ws][t] = __fmul_rn(__fsub_rn(nb.z, nb.x), __fsub_rn(nb.w, nb.y));
        skeep[ws][t] = 1;
    }
    __syncwarp();

    // greedy NMS in sorted order (== global sequential scan within class;
    // cross-class IoU is exactly 0 under the label*4 offset)
    for (int i = 0; i < m; i++) {
        if (skeep[ws][i]) {
            float4 bi = snb[ws][i];
            float  ai = sarea[ws][i];
            for (int t = i + 1 + lane; t < m; t += 32) {
                if (skeep[ws][t]) {
                    float4 bt = snb[ws][t];
                    float lx = fmaxf(bi.x, bt.x), ly = fmaxf(bi.y, bt.y);
                    float rx = fminf(bi.z, bt.z), ry = fminf(bi.w, bt.w);
                    float iw = fmaxf(__fsub_rn(rx, lx), 0.f);
                    float ih = fmaxf(__fsub_rn(ry, ly), 0.f);
                    float inter = __fmul_rn(iw, ih);
                    float den = __fadd_rn(
                        __fsub_rn(__fadd_rn(ai, sarea[ws][t]), inter), 1e-9f);
                    if (__fdiv_rn(inter, den) > IOUT) skeep[ws][t] = 0;
                }
            }
        }
        __syncwarp();
    }

    // push kept keys to the per-image list (rank restored in k_final by key)
    for (int base = 0; base < BCAP; base += 32) {
        int t = base + lane;
        bool k = (t < m) && skeep[ws][t];
        unsigned bal = __ballot_sync(0xFFFFFFFFu, k);
        int cnt = __popc(bal);
        if (cnt) {
            int pos = 0;
            if (lane == 0) pos = atomicAdd(&g_kcount[img], cnt);
            pos = __shfl_sync(0xFFFFFFFFu, pos, 0);
            int rank = pos + __popc(bal & ((1u << lane) - 1u));
            if (k && rank < KCAP) g_kept[(size_t)img * KCAP + rank] = skey[ws][t];
        }
        if (base + 32 >= m) break;
    }
}

// ---------------- K3: bucket-scatter top-300 (7 barriers, no big sort)
// scores in (0.96,1) -> fp32 sign/exponent fixed -> key order ==
// (bucket = key bits [54:43], residual key) lexicographic, descending.
__global__ __launch_bounds__(256) void k_final(const float* __restrict__ pred,
                                               float* __restrict__ out) {
    __shared__ int hist[NBUCK];              // counts -> then exclusive-above offsets
    __shared__ int warp_sum[8], warp_suf[8];
    __shared__ u64 cand[512];
    __shared__ int sB, skc;

    int img  = blockIdx.x;
    int tid  = threadIdx.x;
    int wid  = tid >> 5;
    int lane = tid & 31;

    if (tid == 0) {                          // single-owner read + reset
        int k = g_kcount[img];
        g_kcount[img] = 0;
        skc = (k > KCAP) ? KCAP : k;
        sB = 0;
        if (img == 0) g_hotcnt = 0;          // replay-clean (not read here)
    }
    for (int i = tid; i < NBUCK; i += 256) hist[i] = 0;
    __syncthreads();                                              // BAR1
    int kc = skc;
    int need = (kc < DETN) ? kc : DETN;

    const u64* kept = g_kept + (size_t)img * KCAP;
    for (int i = tid; i < kc; i += 256)
        atomicAdd(&hist[(unsigned)(kept[i] >> 43) & 0xFFFu], 1);
    __syncthreads();                                              // BAR2

    // thread owns 16 consecutive buckets [tid*16, tid*16+16)
    int base = tid * 16;
    int c[16]; int csum = 0;
    #pragma unroll
    for (int j = 0; j < 16; j++) { c[j] = hist[base + j]; csum += c[j]; }

    // warp inclusive-suffix scan of per-thread sums
    int v = csum;
    #pragma unroll
    for (int d = 1; d < 32; d <<= 1) {
        int u = __shfl_down_sync(0xFFFFFFFFu, v, d);
        if (lane + d < 32) v += u;
    }
    if (lane == 0) warp_sum[wid] = v;        // warp total
    __syncthreads();                                              // BAR3
    if (tid < 8) {
        int s = 0;
        for (int w = tid + 1; w < 8; w++) s += warp_sum[w];
        warp_suf[tid] = s;                   // totals of higher warps
    }
    __syncthreads();                                              // BAR4

    // per-bucket exclusive-above offsets (stored back into hist) + find B*
    int run = (v - csum) + warp_suf[wid];    // strictly-above this thread's chunk
    #pragma unroll
    for (int j = 15; j >= 0; j--) {
        int excl = run;
        run += c[j];
        hist[base + j] = excl;
        if (need > 0 && run >= need && excl < need) sB = base + j;  // unique
    }
    __syncthreads();                                              // BAR5

    // scatter keys >= B* into per-bucket slots (disjoint ranges)
    int B = sB;
    for (int i = tid; i < kc; i += 256) {
        u64 key = kept[i];
        int h = (int)((unsigned)(key >> 43) & 0xFFFu);
        if (h >= B) {
            int p = atomicAdd(&hist[h], 1);
            if (p < 512) cand[p] = key;
        }
    }
    __syncthreads();                                              // BAR6

    // deterministic within-bucket order: tiny insertion sorts (desc)
    for (int h = tid; h < NBUCK; h += 256) {
        if (h >= B) {
            int hi = hist[h]; if (hi > 512) hi = 512;
            int lo = (h < NBUCK - 1) ? hist[h + 1] : 0;
            if (lo > 512) lo = 512;
            for (int a = lo + 1; a < hi; a++) {
                u64 key = cand[a];
                int b = a;
                while (b > lo && cand[b - 1] < key) { cand[b] = cand[b - 1]; b--; }
                cand[b] = key;
            }
        }
    }
    __syncthreads();                                              // BAR7

    // decode + write top-300 (rows >= need zeroed)
    for (int r = tid; r < DETN; r += 256) {
        float o0 = 0.f, o1 = 0.f, o2 = 0.f, o3 = 0.f, o4 = 0.f, o5 = 0.f;
        if (r < need) {
            u64 key = cand[r];
            float sc = __uint_as_float((unsigned)(key >> 32));
            unsigned fi = 0xFFFFFFFFu - (unsigned)(key & 0xFFFFFFFFull);
            int anchor = (int)(fi / NCLS);
            int label  = (int)(fi - (unsigned)anchor * NCLS);
            const float* rr = pred + ((size_t)img * NA + anchor) * ROWL;
            float cx = __ldg(rr), cy = __ldg(rr + 1), w2 = __ldg(rr + 2), h2 = __ldg(rr + 3);
            float hw = __fmul_rn(0.5f, w2);
            float hv = __fmul_rn(0.5f, h2);
            o0 = __fsub_rn(cx, hw); o1 = __fsub_rn(cy, hv);
            o2 = __fadd_rn(cx, hw); o3 = __fadd_rn(cy, hv);
            o4 = sc; o5 = (float)label;
        }
        float* dst = out + ((size_t)img * DETN + r) * 6;
        dst[0] = o0; dst[1] = o1; dst[2] = o2;
        dst[3] = o3; dst[4] = o4; dst[5] = o5;
    }
}

// ---------------- launcher ----------------
extern "C" void kernel_launch(void* const* d_in, const int* in_sizes, int n_in,
                              void* d_out, int out_size) {
    const float* pred = (const float*)d_in[0];
    float* out = (float*)d_out;
    (void)in_sizes; (void)n_in; (void)out_size;

    k_scan<<<296, 256>>>(pred);              // 2 blocks/SM, 3 MLP-batched loads/thread
    k_hot<<<252, 256>>>(pred);               // 2016 warps over ~8k hot rows
    k_nms<<<(NIMG * NCLS) / 4, 128>>>(pred); // 160 blocks, 1 warp/(img,cls)
    k_final<<<NIMG, 256>>>(pred, out);       // 7-barrier bucket ranking
}